// round 14
// baseline (speedup 1.0000x reference)
#include <cuda_runtime.h>
#include <cuda_bf16.h>
#include <math.h>

// Problem constants
#define TT   256       // sequence length
#define BB   32        // batch
#define EE   256       // embedding dim
#define HH   512       // hidden dim
#define KTAG 32        // number of tags
#define NEGV (-10000.0f)
#define NBLK_LSTM 128  // persistent blocks (<= SM count, co-resident)

// ---------------- device scratch (static, no allocations) ----------------
__device__ float4  g_x4[TT * (EE / 4) * BB];            // embedded input  [t][e4][b] (float4)
__device__ float   g_xw[(size_t)2 * TT * 4 * HH * BB];  // x @ W_ih^T + b  [d][t][row][b]
__device__ float4  g_hseq[2 * (TT + 1) * (HH / 4) * BB];// h per step      [d][s][k4][b] (write-once)
__device__ float   g_hs[(size_t)2 * TT * HH * BB];      // h per time      [d][t][u][b]
__device__ float   g_feats[TT * BB * KTAG];             // emission feats  [t][b][tag]
__device__ unsigned g_bar;

__device__ __forceinline__ float sigm(float x) { return 1.0f / (1.0f + expf(-x)); }

// Cumulative-counter grid barrier. All NBLK_LSTM blocks are co-resident.
__device__ __forceinline__ void grid_barrier(unsigned target) {
    __syncthreads();
    if (threadIdx.x == 0) {
        __threadfence();                 // release all prior global writes
        atomicAdd(&g_bar, 1u);
        unsigned v;
        do {
            asm volatile("ld.acquire.gpu.u32 %0, [%1];" : "=r"(v) : "l"(&g_bar) : "memory");
        } while (v < target);
    }
    __syncthreads();
}

__global__ void k_reset() { g_bar = 0u; }

// ---------------- 1) embedding gather: x[t][b][:] = emb[sentence[b][t]] ----------------
__global__ void k_embed(const int* __restrict__ sent, const float* __restrict__ emb) {
    int t = blockIdx.x;
    int b = threadIdx.x & 31;
    int w = threadIdx.x >> 5;                  // 0..7
    int tok = sent[b * TT + t];
    const float4* src = (const float4*)(emb + (size_t)tok * EE);
    #pragma unroll
    for (int e4 = w; e4 < EE / 4; e4 += 8) {
        g_x4[(t * (EE / 4) + e4) * BB + b] = src[e4];
    }
}

// ---------------- 2) input GEMM: xw[d][t][row][b] = dot(x[t][b], W_ih[d][row]) + bias ----------------
// block = (d, t, unit-tile of 8); thread (b, y) computes the 4 gate rows of unit u = u0+y.
__global__ void __launch_bounds__(256) k_xw(
    const float* __restrict__ Wf, const float* __restrict__ bf,
    const float* __restrict__ Wb, const float* __restrict__ bbias)
{
    int bi  = blockIdx.x;
    int d   = bi >> 14;              // 16384 blocks per dir
    int rem = bi & 16383;
    int t   = rem >> 6;
    int u0  = (rem & 63) * 8;
    int b   = threadIdx.x & 31;
    int y   = threadIdx.x >> 5;
    int u   = u0 + y;

    const float* W    = d ? Wb : Wf;
    const float* bias = d ? bbias : bf;
    const float4* w0 = (const float4*)(W + (size_t)(0 * HH + u) * EE);
    const float4* w1 = (const float4*)(W + (size_t)(1 * HH + u) * EE);
    const float4* w2 = (const float4*)(W + (size_t)(2 * HH + u) * EE);
    const float4* w3 = (const float4*)(W + (size_t)(3 * HH + u) * EE);
    const float4* xp = &g_x4[t * (EE / 4) * BB + b];

    float a0 = 0.f, a1 = 0.f, a2 = 0.f, a3 = 0.f;
    #pragma unroll 2
    for (int k4 = 0; k4 < EE / 4; k4++) {
        float4 xv = xp[k4 * BB];
        float4 v0 = __ldg(&w0[k4]);
        float4 v1 = __ldg(&w1[k4]);
        float4 v2 = __ldg(&w2[k4]);
        float4 v3 = __ldg(&w3[k4]);
        a0 += xv.x * v0.x + xv.y * v0.y + xv.z * v0.z + xv.w * v0.w;
        a1 += xv.x * v1.x + xv.y * v1.y + xv.z * v1.z + xv.w * v1.w;
        a2 += xv.x * v2.x + xv.y * v2.y + xv.z * v2.z + xv.w * v2.w;
        a3 += xv.x * v3.x + xv.y * v3.y + xv.z * v3.z + xv.w * v3.w;
    }
    size_t base = ((size_t)d * TT + t) * (size_t)(4 * HH) * BB;
    g_xw[base + (size_t)(0 * HH + u) * BB + b] = a0 + bias[0 * HH + u];
    g_xw[base + (size_t)(1 * HH + u) * BB + b] = a1 + bias[1 * HH + u];
    g_xw[base + (size_t)(2 * HH + u) * BB + b] = a2 + bias[2 * HH + u];
    g_xw[base + (size_t)(3 * HH + u) * BB + b] = a3 + bias[3 * HH + u];
}

// ---------------- 3) persistent bidirectional LSTM ----------------
// 128 blocks: (dir, unit-tile of 8). Thread (b,y) owns unit u for batch b:
// its 4 gate rows, its cell state (register), writes h each step.
__global__ void __launch_bounds__(256) k_lstm(
    const float* __restrict__ Whf, const float* __restrict__ Whb,
    const float* __restrict__ h0, const float* __restrict__ c0)
{
    int bi = blockIdx.x;
    int d  = bi >> 6;
    int u0 = (bi & 63) * 8;
    int b  = threadIdx.x & 31;
    int y  = threadIdx.x >> 5;
    int u  = u0 + y;

    const float* Wh = d ? Whb : Whf;
    const float4* w0 = (const float4*)(Wh + (size_t)(0 * HH + u) * HH);
    const float4* w1 = (const float4*)(Wh + (size_t)(1 * HH + u) * HH);
    const float4* w2 = (const float4*)(Wh + (size_t)(2 * HH + u) * HH);
    const float4* w3 = (const float4*)(Wh + (size_t)(3 * HH + u) * HH);

    float c = c0[((size_t)d * BB + b) * HH + u];
    float h = h0[((size_t)d * BB + b) * HH + u];

    float* hseqf = (float*)g_hseq;
    // publish initial h into slot s=0
    {
        size_t f4 = (((size_t)d * (TT + 1) + 0) * (HH / 4) + (u >> 2)) * BB + b;
        hseqf[f4 * 4 + (u & 3)] = h;
    }
    grid_barrier(NBLK_LSTM * 1u);

    for (int s = 0; s < TT; s++) {
        int t = d ? (TT - 1 - s) : s;

        size_t xwbase = ((size_t)d * TT + t) * (size_t)(4 * HH) * BB;
        float x0 = g_xw[xwbase + (size_t)(0 * HH + u) * BB + b];
        float x1 = g_xw[xwbase + (size_t)(1 * HH + u) * BB + b];
        float x2 = g_xw[xwbase + (size_t)(2 * HH + u) * BB + b];
        float x3 = g_xw[xwbase + (size_t)(3 * HH + u) * BB + b];

        const float4* hp = &g_hseq[((size_t)d * (TT + 1) + s) * (HH / 4) * BB + b];

        float a0 = 0.f, a1 = 0.f, a2 = 0.f, a3 = 0.f;
        #pragma unroll 2
        for (int k4 = 0; k4 < HH / 4; k4++) {
            float4 hv = hp[k4 * BB];
            float4 v0 = __ldg(&w0[k4]);
            float4 v1 = __ldg(&w1[k4]);
            float4 v2 = __ldg(&w2[k4]);
            float4 v3 = __ldg(&w3[k4]);
            a0 += hv.x * v0.x + hv.y * v0.y + hv.z * v0.z + hv.w * v0.w;
            a1 += hv.x * v1.x + hv.y * v1.y + hv.z * v1.z + hv.w * v1.w;
            a2 += hv.x * v2.x + hv.y * v2.y + hv.z * v2.z + hv.w * v2.w;
            a3 += hv.x * v3.x + hv.y * v3.y + hv.z * v3.z + hv.w * v3.w;
        }
        a0 += x0; a1 += x1; a2 += x2; a3 += x3;

        float ig = sigm(a0);
        float fg = sigm(a1);
        float gg = tanhf(a2);
        float og = sigm(a3);
        c = fg * c + ig * gg;
        h = og * tanhf(c);

        size_t f4 = (((size_t)d * (TT + 1) + (s + 1)) * (HH / 4) + (u >> 2)) * BB + b;
        hseqf[f4 * 4 + (u & 3)] = h;
        g_hs[(((size_t)d * TT + t) * HH + u) * BB + b] = h;

        grid_barrier((unsigned)NBLK_LSTM * (unsigned)(s + 2));
    }
}

// ---------------- 4) emission features: feats[t][b][k] = concat(hf,hb) @ W_out^T + b_out ----------------
__global__ void __launch_bounds__(256) k_feats(
    const float* __restrict__ Wout, const float* __restrict__ bout)
{
    int t = blockIdx.x;
    int b = threadIdx.x & 31;
    int y = threadIdx.x >> 5;     // 0..7
    int tag0 = y * 4;

    float a0 = 0.f, a1 = 0.f, a2 = 0.f, a3 = 0.f;
    #pragma unroll
    for (int d = 0; d < 2; d++) {
        const float* hb = g_hs + (((size_t)d * TT + t) * HH) * BB + b;
        const float4* w0 = (const float4*)(Wout + (size_t)(tag0 + 0) * (2 * HH) + d * HH);
        const float4* w1 = (const float4*)(Wout + (size_t)(tag0 + 1) * (2 * HH) + d * HH);
        const float4* w2 = (const float4*)(Wout + (size_t)(tag0 + 2) * (2 * HH) + d * HH);
        const float4* w3 = (const float4*)(Wout + (size_t)(tag0 + 3) * (2 * HH) + d * HH);
        #pragma unroll 2
        for (int j4 = 0; j4 < HH / 4; j4++) {
            float hv0 = hb[(j4 * 4 + 0) * BB];
            float hv1 = hb[(j4 * 4 + 1) * BB];
            float hv2 = hb[(j4 * 4 + 2) * BB];
            float hv3 = hb[(j4 * 4 + 3) * BB];
            float4 v0 = __ldg(&w0[j4]);
            float4 v1 = __ldg(&w1[j4]);
            float4 v2 = __ldg(&w2[j4]);
            float4 v3 = __ldg(&w3[j4]);
            a0 += hv0 * v0.x + hv1 * v0.y + hv2 * v0.z + hv3 * v0.w;
            a1 += hv0 * v1.x + hv1 * v1.y + hv2 * v1.z + hv3 * v1.w;
            a2 += hv0 * v2.x + hv1 * v2.y + hv2 * v2.z + hv3 * v2.w;
            a3 += hv0 * v3.x + hv1 * v3.y + hv2 * v3.z + hv3 * v3.w;
        }
    }
    size_t ob = ((size_t)t * BB + b) * KTAG + tag0;
    g_feats[ob + 0] = a0 + bout[tag0 + 0];
    g_feats[ob + 1] = a1 + bout[tag0 + 1];
    g_feats[ob + 2] = a2 + bout[tag0 + 2];
    g_feats[ob + 3] = a3 + bout[tag0 + 3];
}

// ---------------- 5) Viterbi decode: one block per batch ----------------
__global__ void __launch_bounds__(1024) k_viterbi(
    const float* __restrict__ trans, float* __restrict__ out, int out_size)
{
    __shared__ float tr[KTAG * KTAG];
    __shared__ float v[2][KTAG];
    __shared__ unsigned char bp[TT][KTAG];

    int b   = blockIdx.x;
    int tid = threadIdx.x;
    int prev = tid & 31;      // lane
    int nxt  = tid >> 5;      // warp == next tag

    tr[tid] = trans[tid];
    if (tid < KTAG) v[0][tid] = (tid == 30) ? 0.0f : NEGV;   // START=30
    __syncthreads();

    for (int t = 0; t < TT; t++) {
        int p = t & 1;
        float sc = v[p][prev] + tr[nxt * KTAG + prev];
        int idx = prev;
        #pragma unroll
        for (int off = 16; off; off >>= 1) {
            float ov = __shfl_down_sync(0xffffffffu, sc, off);
            int   oi = __shfl_down_sync(0xffffffffu, idx, off);
            if (ov > sc || (ov == sc && oi < idx)) { sc = ov; idx = oi; }
        }
        if (prev == 0) {
            bp[t][nxt] = (unsigned char)idx;
            v[p ^ 1][nxt] = sc + g_feats[((size_t)t * BB + b) * KTAG + nxt];
        }
        __syncthreads();
    }

    // terminal = v_final + transitions[STOP=31][:]; v_final parity = 0 (TT even)
    if (tid < 32) {
        float term = v[0][tid] + tr[31 * KTAG + tid];
        int idx = tid;
        #pragma unroll
        for (int off = 16; off; off >>= 1) {
            float ov = __shfl_down_sync(0xffffffffu, term, off);
            int   oi = __shfl_down_sync(0xffffffffu, idx, off);
            if (ov > term || (ov == term && oi < idx)) { term = ov; idx = oi; }
        }
        if (tid == 0) {
            bool both = (out_size >= BB * (TT + 1));
            if (both || out_size == BB) out[b] = term;   // path_score
            if (both) {
                int base = BB + b * TT;
                int tag = idx;
                for (int t = TT - 1; t >= 0; t--) {
                    out[base + t] = (float)tag;
                    tag = bp[t][tag];
                }
            } else if (out_size == BB * TT) {
                int tag = idx;
                for (int t = TT - 1; t >= 0; t--) {
                    out[b * TT + t] = (float)tag;
                    tag = bp[t][tag];
                }
            }
        }
    }
}

// ---------------- launch ----------------
extern "C" void kernel_launch(void* const* d_in, const int* in_sizes, int n_in,
                              void* d_out, int out_size) {
    const int*   sent = (const int*)  d_in[0];
    const float* emb  = (const float*)d_in[1];
    const float* Wif  = (const float*)d_in[2];
    const float* Whf  = (const float*)d_in[3];
    const float* bf   = (const float*)d_in[4];
    const float* Wib  = (const float*)d_in[5];
    const float* Whb  = (const float*)d_in[6];
    const float* bb   = (const float*)d_in[7];
    const float* Wout = (const float*)d_in[8];
    const float* bout = (const float*)d_in[9];
    const float* trans= (const float*)d_in[10];
    const float* h0   = (const float*)d_in[11];
    const float* c0   = (const float*)d_in[12];
    (void)in_sizes; (void)n_in;

    k_reset  <<<1, 1>>>();
    k_embed  <<<TT, 256>>>(sent, emb);
    k_xw     <<<2 * TT * 64, 256>>>(Wif, bf, Wib, bb);
    k_lstm   <<<NBLK_LSTM, 256>>>(Whf, Whb, h0, c0);
    k_feats  <<<TT, 256>>>(Wout, bout);
    k_viterbi<<<BB, 1024>>>(trans, (float*)d_out, out_size);
}

// round 15
// speedup vs baseline: 3.8555x; 3.8555x over previous
#include <cuda_runtime.h>
#include <cuda_bf16.h>
#include <math.h>

// Problem constants
#define TT   256       // sequence length
#define BB   32        // batch
#define EE   256       // embedding dim
#define HH   512       // hidden dim
#define KTAG 32        // number of tags
#define NEGV (-10000.0f)
#define NBLK_LSTM 128  // persistent blocks (<= SM count, co-resident)

// ---------------- device scratch (static, no allocations) ----------------
__device__ float4  g_x4[TT * (EE / 4) * BB];              // embedded input  [t][e4][b]
__device__ float4  g_xw4[(size_t)2 * TT * HH * BB];       // xW_ih^T + b     [d][t][u][b] = (i,f,g,o)
__device__ float4  g_hseq[2 * (TT + 1) * (HH / 4) * BB];  // h per step      [d][s][k4][b] (write-once)
__device__ float   g_feats[TT * BB * KTAG];               // emission feats  [t][b][tag]
__device__ unsigned g_bar;

__device__ __forceinline__ float sigm(float x) { return 1.0f / (1.0f + expf(-x)); }

// Cumulative-counter grid barrier. All NBLK_LSTM blocks are co-resident.
__device__ __forceinline__ void grid_barrier(unsigned target) {
    __syncthreads();
    if (threadIdx.x == 0) {
        __threadfence();                 // release all prior global writes
        atomicAdd(&g_bar, 1u);
        unsigned v;
        do {
            asm volatile("ld.acquire.gpu.u32 %0, [%1];" : "=r"(v) : "l"(&g_bar) : "memory");
        } while (v < target);
    }
    __syncthreads();
}

__global__ void k_reset() { g_bar = 0u; }

// ---------------- 1) embedding gather ----------------
__global__ void k_embed(const int* __restrict__ sent, const float* __restrict__ emb) {
    int t = blockIdx.x;
    int b = threadIdx.x & 31;
    int w = threadIdx.x >> 5;                  // 0..7
    int tok = sent[b * TT + t];
    const float4* src = (const float4*)(emb + (size_t)tok * EE);
    #pragma unroll
    for (int e4 = w; e4 < EE / 4; e4 += 8) {
        g_x4[(t * (EE / 4) + e4) * BB + b] = src[e4];
    }
}

// ---------------- 2) input GEMM: 4 timesteps per thread, float4 (i,f,g,o) output ----------------
// grid = 2 dirs * 64 t-tiles(4 each) * 64 u-tiles(8 units) = 8192 blocks
__global__ void __launch_bounds__(256, 1) k_xw(
    const float* __restrict__ Wf, const float* __restrict__ bf,
    const float* __restrict__ Wb, const float* __restrict__ bbias)
{
    int bi  = blockIdx.x;
    int d   = bi >> 12;
    int rem = bi & 4095;
    int t0  = (rem >> 6) * 4;
    int u0  = (rem & 63) * 8;
    int b   = threadIdx.x & 31;
    int y   = threadIdx.x >> 5;
    int u   = u0 + y;

    const float* W    = d ? Wb : Wf;
    const float* bias = d ? bbias : bf;
    const float4* w0 = (const float4*)(W + (size_t)(0 * HH + u) * EE);
    const float4* w1 = (const float4*)(W + (size_t)(1 * HH + u) * EE);
    const float4* w2 = (const float4*)(W + (size_t)(2 * HH + u) * EE);
    const float4* w3 = (const float4*)(W + (size_t)(3 * HH + u) * EE);
    const float4* xp0 = &g_x4[(t0 + 0) * (EE / 4) * BB + b];
    const float4* xp1 = &g_x4[(t0 + 1) * (EE / 4) * BB + b];
    const float4* xp2 = &g_x4[(t0 + 2) * (EE / 4) * BB + b];
    const float4* xp3 = &g_x4[(t0 + 3) * (EE / 4) * BB + b];

    float a[4][4];
    #pragma unroll
    for (int i = 0; i < 4; i++)
        #pragma unroll
        for (int j = 0; j < 4; j++) a[i][j] = 0.f;

    #pragma unroll 2
    for (int k4 = 0; k4 < EE / 4; k4++) {
        float4 v0 = __ldg(&w0[k4]);
        float4 v1 = __ldg(&w1[k4]);
        float4 v2 = __ldg(&w2[k4]);
        float4 v3 = __ldg(&w3[k4]);
        float4 xv;
        xv = xp0[k4 * BB];
        a[0][0] += xv.x*v0.x + xv.y*v0.y + xv.z*v0.z + xv.w*v0.w;
        a[0][1] += xv.x*v1.x + xv.y*v1.y + xv.z*v1.z + xv.w*v1.w;
        a[0][2] += xv.x*v2.x + xv.y*v2.y + xv.z*v2.z + xv.w*v2.w;
        a[0][3] += xv.x*v3.x + xv.y*v3.y + xv.z*v3.z + xv.w*v3.w;
        xv = xp1[k4 * BB];
        a[1][0] += xv.x*v0.x + xv.y*v0.y + xv.z*v0.z + xv.w*v0.w;
        a[1][1] += xv.x*v1.x + xv.y*v1.y + xv.z*v1.z + xv.w*v1.w;
        a[1][2] += xv.x*v2.x + xv.y*v2.y + xv.z*v2.z + xv.w*v2.w;
        a[1][3] += xv.x*v3.x + xv.y*v3.y + xv.z*v3.z + xv.w*v3.w;
        xv = xp2[k4 * BB];
        a[2][0] += xv.x*v0.x + xv.y*v0.y + xv.z*v0.z + xv.w*v0.w;
        a[2][1] += xv.x*v1.x + xv.y*v1.y + xv.z*v1.z + xv.w*v1.w;
        a[2][2] += xv.x*v2.x + xv.y*v2.y + xv.z*v2.z + xv.w*v2.w;
        a[2][3] += xv.x*v3.x + xv.y*v3.y + xv.z*v3.z + xv.w*v3.w;
        xv = xp3[k4 * BB];
        a[3][0] += xv.x*v0.x + xv.y*v0.y + xv.z*v0.z + xv.w*v0.w;
        a[3][1] += xv.x*v1.x + xv.y*v1.y + xv.z*v1.z + xv.w*v1.w;
        a[3][2] += xv.x*v2.x + xv.y*v2.y + xv.z*v2.z + xv.w*v2.w;
        a[3][3] += xv.x*v3.x + xv.y*v3.y + xv.z*v3.z + xv.w*v3.w;
    }

    float bi0 = bias[0 * HH + u];
    float bi1 = bias[1 * HH + u];
    float bi2 = bias[2 * HH + u];
    float bi3 = bias[3 * HH + u];
    #pragma unroll
    for (int tt = 0; tt < 4; tt++) {
        size_t o = (((size_t)d * TT + (t0 + tt)) * HH + u) * BB + b;
        g_xw4[o] = make_float4(a[tt][0] + bi0, a[tt][1] + bi1, a[tt][2] + bi2, a[tt][3] + bi3);
    }
}

// ---------------- 3) persistent bidirectional LSTM (weights in SMEM) ----------------
// 128 blocks: (dir, 8-unit tile). Warp y owns unit u for all 32 batches (lane = b).
// 64 KB dynamic smem = this block's 32 gate rows (float4 over k).
__global__ void __launch_bounds__(256, 1) k_lstm(
    const float* __restrict__ Whf, const float* __restrict__ Whb,
    const float* __restrict__ h0, const float* __restrict__ c0)
{
    extern __shared__ float4 s_w[];   // [y(8)][gate(4)][k4(128)]

    int bi = blockIdx.x;
    int d  = bi >> 6;
    int u0 = (bi & 63) * 8;
    int b  = threadIdx.x & 31;
    int y  = threadIdx.x >> 5;
    int u  = u0 + y;

    const float4* Wh4 = (const float4*)(d ? Whb : Whf);  // rows of 128 float4

    // cooperative weight load: 4096 float4, 16 per thread
    #pragma unroll
    for (int i = threadIdx.x; i < 8 * 4 * 128; i += 256) {
        int yy = i >> 9;            // /512
        int g  = (i >> 7) & 3;      // /128 %4
        int k4 = i & 127;
        s_w[i] = Wh4[((size_t)(g * HH + u0 + yy)) * 128 + k4];
    }

    float c = c0[((size_t)d * BB + b) * HH + u];
    float h = h0[((size_t)d * BB + b) * HH + u];

    float* hseqf = (float*)g_hseq;
    // publish initial h into slot s=0
    {
        size_t f4 = (((size_t)d * (TT + 1) + 0) * (HH / 4) + (u >> 2)) * BB + b;
        hseqf[f4 * 4 + (u & 3)] = h;
    }
    grid_barrier(NBLK_LSTM * 1u);   // also covers the smem load via its __syncthreads

    const float4* swy = s_w + y * 4 * 128;

    for (int s = 0; s < TT; s++) {
        int t = d ? (TT - 1 - s) : s;

        float4 xv = g_xw4[(((size_t)d * TT + t) * HH + u) * BB + b];
        float a0 = xv.x, a1 = xv.y, a2 = xv.z, a3 = xv.w;

        const float4* hp = &g_hseq[(((size_t)d * (TT + 1) + s) * (HH / 4)) * BB + b];

        #pragma unroll 8
        for (int k4 = 0; k4 < HH / 4; k4++) {
            float4 hv = hp[k4 * BB];
            float4 v0 = swy[0 * 128 + k4];
            float4 v1 = swy[1 * 128 + k4];
            float4 v2 = swy[2 * 128 + k4];
            float4 v3 = swy[3 * 128 + k4];
            a0 += hv.x*v0.x + hv.y*v0.y + hv.z*v0.z + hv.w*v0.w;
            a1 += hv.x*v1.x + hv.y*v1.y + hv.z*v1.z + hv.w*v1.w;
            a2 += hv.x*v2.x + hv.y*v2.y + hv.z*v2.z + hv.w*v2.w;
            a3 += hv.x*v3.x + hv.y*v3.y + hv.z*v3.z + hv.w*v3.w;
        }

        float ig = sigm(a0);
        float fg = sigm(a1);
        float gg = tanhf(a2);
        float og = sigm(a3);
        c = fg * c + ig * gg;
        h = og * tanhf(c);

        size_t f4 = (((size_t)d * (TT + 1) + (s + 1)) * (HH / 4) + (u >> 2)) * BB + b;
        hseqf[f4 * 4 + (u & 3)] = h;

        grid_barrier((unsigned)NBLK_LSTM * (unsigned)(s + 2));
    }
}

// ---------------- 4) emission features from g_hseq ----------------
__global__ void __launch_bounds__(256) k_feats(
    const float* __restrict__ Wout, const float* __restrict__ bout)
{
    int t = blockIdx.x;
    int b = threadIdx.x & 31;
    int y = threadIdx.x >> 5;     // 0..7
    int tag0 = y * 4;

    float a0 = 0.f, a1 = 0.f, a2 = 0.f, a3 = 0.f;
    #pragma unroll
    for (int d = 0; d < 2; d++) {
        int s_idx = d ? (TT - t) : (t + 1);   // h at time t, direction d
        const float4* hb = &g_hseq[(((size_t)d * (TT + 1) + s_idx) * (HH / 4)) * BB + b];
        const float4* w0 = (const float4*)(Wout + (size_t)(tag0 + 0) * (2 * HH) + d * HH);
        const float4* w1 = (const float4*)(Wout + (size_t)(tag0 + 1) * (2 * HH) + d * HH);
        const float4* w2 = (const float4*)(Wout + (size_t)(tag0 + 2) * (2 * HH) + d * HH);
        const float4* w3 = (const float4*)(Wout + (size_t)(tag0 + 3) * (2 * HH) + d * HH);
        #pragma unroll 4
        for (int j4 = 0; j4 < HH / 4; j4++) {
            float4 hv = hb[j4 * BB];          // h[4j4..4j4+3][b]
            float4 v0 = __ldg(&w0[j4]);
            float4 v1 = __ldg(&w1[j4]);
            float4 v2 = __ldg(&w2[j4]);
            float4 v3 = __ldg(&w3[j4]);
            a0 += hv.x*v0.x + hv.y*v0.y + hv.z*v0.z + hv.w*v0.w;
            a1 += hv.x*v1.x + hv.y*v1.y + hv.z*v1.z + hv.w*v1.w;
            a2 += hv.x*v2.x + hv.y*v2.y + hv.z*v2.z + hv.w*v2.w;
            a3 += hv.x*v3.x + hv.y*v3.y + hv.z*v3.z + hv.w*v3.w;
        }
    }
    size_t ob = ((size_t)t * BB + b) * KTAG + tag0;
    g_feats[ob + 0] = a0 + bout[tag0 + 0];
    g_feats[ob + 1] = a1 + bout[tag0 + 1];
    g_feats[ob + 2] = a2 + bout[tag0 + 2];
    g_feats[ob + 3] = a3 + bout[tag0 + 3];
}

// ---------------- 5) Viterbi decode: one block per batch ----------------
__global__ void __launch_bounds__(1024) k_viterbi(
    const float* __restrict__ trans, float* __restrict__ out, int out_size)
{
    __shared__ float tr[KTAG * KTAG];
    __shared__ float v[2][KTAG];
    __shared__ unsigned char bp[TT][KTAG];

    int b   = blockIdx.x;
    int tid = threadIdx.x;
    int prev = tid & 31;      // lane
    int nxt  = tid >> 5;      // warp == next tag

    tr[tid] = trans[tid];
    if (tid < KTAG) v[0][tid] = (tid == 30) ? 0.0f : NEGV;   // START=30
    __syncthreads();

    for (int t = 0; t < TT; t++) {
        int p = t & 1;
        float sc = v[p][prev] + tr[nxt * KTAG + prev];
        int idx = prev;
        #pragma unroll
        for (int off = 16; off; off >>= 1) {
            float ov = __shfl_down_sync(0xffffffffu, sc, off);
            int   oi = __shfl_down_sync(0xffffffffu, idx, off);
            if (ov > sc || (ov == sc && oi < idx)) { sc = ov; idx = oi; }
        }
        if (prev == 0) {
            bp[t][nxt] = (unsigned char)idx;
            v[p ^ 1][nxt] = sc + g_feats[((size_t)t * BB + b) * KTAG + nxt];
        }
        __syncthreads();
    }

    // terminal = v_final + transitions[STOP=31][:]; v_final parity = 0 (TT even)
    if (tid < 32) {
        float term = v[0][tid] + tr[31 * KTAG + tid];
        int idx = tid;
        #pragma unroll
        for (int off = 16; off; off >>= 1) {
            float ov = __shfl_down_sync(0xffffffffu, term, off);
            int   oi = __shfl_down_sync(0xffffffffu, idx, off);
            if (ov > term || (ov == term && oi < idx)) { term = ov; idx = oi; }
        }
        if (tid == 0) {
            bool both = (out_size >= BB * (TT + 1));
            if (both || out_size == BB) out[b] = term;   // path_score
            if (both) {
                int base = BB + b * TT;
                int tag = idx;
                for (int t = TT - 1; t >= 0; t--) {
                    out[base + t] = (float)tag;
                    tag = bp[t][tag];
                }
            } else if (out_size == BB * TT) {
                int tag = idx;
                for (int t = TT - 1; t >= 0; t--) {
                    out[b * TT + t] = (float)tag;
                    tag = bp[t][tag];
                }
            }
        }
    }
}

// ---------------- launch ----------------
extern "C" void kernel_launch(void* const* d_in, const int* in_sizes, int n_in,
                              void* d_out, int out_size) {
    const int*   sent = (const int*)  d_in[0];
    const float* emb  = (const float*)d_in[1];
    const float* Wif  = (const float*)d_in[2];
    const float* Whf  = (const float*)d_in[3];
    const float* bf   = (const float*)d_in[4];
    const float* Wib  = (const float*)d_in[5];
    const float* Whb  = (const float*)d_in[6];
    const float* bb   = (const float*)d_in[7];
    const float* Wout = (const float*)d_in[8];
    const float* bout = (const float*)d_in[9];
    const float* trans= (const float*)d_in[10];
    const float* h0   = (const float*)d_in[11];
    const float* c0   = (const float*)d_in[12];
    (void)in_sizes; (void)n_in;

    const int LSTM_SMEM = 8 * 4 * 128 * 16;   // 64 KB
    cudaFuncSetAttribute(k_lstm, cudaFuncAttributeMaxDynamicSharedMemorySize, LSTM_SMEM);

    k_reset  <<<1, 1>>>();
    k_embed  <<<TT, 256>>>(sent, emb);
    k_xw     <<<2 * 64 * 64, 256>>>(Wif, bf, Wib, bb);
    k_lstm   <<<NBLK_LSTM, 256, LSTM_SMEM>>>(Whf, Whb, h0, c0);
    k_feats  <<<TT, 256>>>(Wout, bout);
    k_viterbi<<<BB, 1024>>>(trans, (float*)d_out, out_size);
}

// round 16
// speedup vs baseline: 4.2293x; 1.0969x over previous
#include <cuda_runtime.h>
#include <cuda_bf16.h>
#include <math.h>

// Problem constants
#define TT   256       // sequence length
#define BB   32        // batch
#define EE   256       // embedding dim
#define HH   512       // hidden dim
#define KTAG 32        // number of tags
#define NEGV (-10000.0f)
#define NBLK_DIR 64    // persistent blocks per direction (128 total, co-resident)

// ---------------- device scratch (static, no allocations) ----------------
__device__ float4  g_x4[TT * (EE / 4) * BB];              // embedded input  [t][e4][b]
__device__ float4  g_xw4[(size_t)2 * TT * HH * BB];       // xW_ih^T + b     [d][t][u][b] = (i,f,g,o)
__device__ float4  g_hseq[2 * (TT + 1) * (HH / 4) * BB];  // h per step      [d][s][k4][b] (write-once)
__device__ float   g_feats[TT * BB * KTAG];               // emission feats  [t][b][tag]
__device__ unsigned g_bar[2];                             // one barrier counter per direction

__device__ __forceinline__ float sigm(float x) { return 1.0f / (1.0f + expf(-x)); }

// packed fp32x2 FMA (sm_103a): a = x*y + a elementwise on two packed floats
__device__ __forceinline__ void ffma2(unsigned long long& a, unsigned long long x, unsigned long long y) {
    asm("fma.rn.f32x2 %0, %1, %2, %0;" : "+l"(a) : "l"(x), "l"(y));
}
__device__ __forceinline__ float hsum2(unsigned long long a) {
    float lo, hi;
    asm("mov.b64 {%0,%1}, %2;" : "=f"(lo), "=f"(hi) : "l"(a));
    return lo + hi;
}

// Cumulative-counter barrier over the NBLK_DIR blocks of one direction.
__device__ __forceinline__ void grid_barrier(unsigned* bar, unsigned target) {
    __syncthreads();
    if (threadIdx.x == 0) {
        __threadfence();                 // release all prior global writes
        atomicAdd(bar, 1u);
        unsigned v;
        do {
            asm volatile("ld.acquire.gpu.u32 %0, [%1];" : "=r"(v) : "l"(bar) : "memory");
        } while (v < target);
    }
    __syncthreads();
}

__global__ void k_reset() { g_bar[0] = 0u; g_bar[1] = 0u; }

// ---------------- 1) embedding gather ----------------
__global__ void k_embed(const int* __restrict__ sent, const float* __restrict__ emb) {
    int t = blockIdx.x;
    int b = threadIdx.x & 31;
    int w = threadIdx.x >> 5;                  // 0..7
    int tok = sent[b * TT + t];
    const float4* src = (const float4*)(emb + (size_t)tok * EE);
    #pragma unroll
    for (int e4 = w; e4 < EE / 4; e4 += 8) {
        g_x4[(t * (EE / 4) + e4) * BB + b] = src[e4];
    }
}

// ---------------- 2) input GEMM: 4 timesteps/thread, f32x2 FMA, float4 (i,f,g,o) output ----------------
// grid = 2 dirs * 64 t-tiles(4 each) * 64 u-tiles(8 units) = 8192 blocks
__global__ void __launch_bounds__(256, 1) k_xw(
    const float* __restrict__ Wf, const float* __restrict__ bf,
    const float* __restrict__ Wb, const float* __restrict__ bbias)
{
    int bi  = blockIdx.x;
    int d   = bi >> 12;
    int rem = bi & 4095;
    int t0  = (rem >> 6) * 4;
    int u0  = (rem & 63) * 8;
    int b   = threadIdx.x & 31;
    int y   = threadIdx.x >> 5;
    int u   = u0 + y;

    const float* W    = d ? Wb : Wf;
    const float* bias = d ? bbias : bf;
    const ulonglong2* w0 = (const ulonglong2*)(W + (size_t)(0 * HH + u) * EE);
    const ulonglong2* w1 = (const ulonglong2*)(W + (size_t)(1 * HH + u) * EE);
    const ulonglong2* w2 = (const ulonglong2*)(W + (size_t)(2 * HH + u) * EE);
    const ulonglong2* w3 = (const ulonglong2*)(W + (size_t)(3 * HH + u) * EE);
    const ulonglong2* xp0 = (const ulonglong2*)&g_x4[(t0 + 0) * (EE / 4) * BB + b];
    const ulonglong2* xp1 = (const ulonglong2*)&g_x4[(t0 + 1) * (EE / 4) * BB + b];
    const ulonglong2* xp2 = (const ulonglong2*)&g_x4[(t0 + 2) * (EE / 4) * BB + b];
    const ulonglong2* xp3 = (const ulonglong2*)&g_x4[(t0 + 3) * (EE / 4) * BB + b];

    unsigned long long A[4][4];   // [t][gate] packed f32x2 accumulators
    #pragma unroll
    for (int i = 0; i < 4; i++)
        #pragma unroll
        for (int j = 0; j < 4; j++) A[i][j] = 0ULL;

    #pragma unroll 4
    for (int k4 = 0; k4 < EE / 4; k4++) {
        ulonglong2 v0 = __ldg(&w0[k4]);
        ulonglong2 v1 = __ldg(&w1[k4]);
        ulonglong2 v2 = __ldg(&w2[k4]);
        ulonglong2 v3 = __ldg(&w3[k4]);
        ulonglong2 xv;
        xv = xp0[k4 * BB];
        ffma2(A[0][0], xv.x, v0.x); ffma2(A[0][0], xv.y, v0.y);
        ffma2(A[0][1], xv.x, v1.x); ffma2(A[0][1], xv.y, v1.y);
        ffma2(A[0][2], xv.x, v2.x); ffma2(A[0][2], xv.y, v2.y);
        ffma2(A[0][3], xv.x, v3.x); ffma2(A[0][3], xv.y, v3.y);
        xv = xp1[k4 * BB];
        ffma2(A[1][0], xv.x, v0.x); ffma2(A[1][0], xv.y, v0.y);
        ffma2(A[1][1], xv.x, v1.x); ffma2(A[1][1], xv.y, v1.y);
        ffma2(A[1][2], xv.x, v2.x); ffma2(A[1][2], xv.y, v2.y);
        ffma2(A[1][3], xv.x, v3.x); ffma2(A[1][3], xv.y, v3.y);
        xv = xp2[k4 * BB];
        ffma2(A[2][0], xv.x, v0.x); ffma2(A[2][0], xv.y, v0.y);
        ffma2(A[2][1], xv.x, v1.x); ffma2(A[2][1], xv.y, v1.y);
        ffma2(A[2][2], xv.x, v2.x); ffma2(A[2][2], xv.y, v2.y);
        ffma2(A[2][3], xv.x, v3.x); ffma2(A[2][3], xv.y, v3.y);
        xv = xp3[k4 * BB];
        ffma2(A[3][0], xv.x, v0.x); ffma2(A[3][0], xv.y, v0.y);
        ffma2(A[3][1], xv.x, v1.x); ffma2(A[3][1], xv.y, v1.y);
        ffma2(A[3][2], xv.x, v2.x); ffma2(A[3][2], xv.y, v2.y);
        ffma2(A[3][3], xv.x, v3.x); ffma2(A[3][3], xv.y, v3.y);
    }

    float bi0 = bias[0 * HH + u];
    float bi1 = bias[1 * HH + u];
    float bi2 = bias[2 * HH + u];
    float bi3 = bias[3 * HH + u];
    #pragma unroll
    for (int tt = 0; tt < 4; tt++) {
        size_t o = (((size_t)d * TT + (t0 + tt)) * HH + u) * BB + b;
        g_xw4[o] = make_float4(hsum2(A[tt][0]) + bi0, hsum2(A[tt][1]) + bi1,
                               hsum2(A[tt][2]) + bi2, hsum2(A[tt][3]) + bi3);
    }
}

// ---------------- 3) persistent bidirectional LSTM ----------------
// 128 blocks x 512 threads: (dir, 8-unit tile). Thread = (b, y=unit, z=k-half).
// Each (u,b) is computed by 2 threads splitting k; partials combined in smem.
__global__ void __launch_bounds__(512, 1) k_lstm(
    const float* __restrict__ Whf, const float* __restrict__ Whb,
    const float* __restrict__ h0, const float* __restrict__ c0)
{
    extern __shared__ float4 s_w4[];                 // 4096 float4 = 64 KB weights
    float4* s_red = s_w4 + 8 * 4 * 128;              // 256 float4 = 4 KB partials

    int bi = blockIdx.x;
    int d  = bi >> 6;
    int u0 = (bi & 63) * 8;
    int b  = threadIdx.x & 31;
    int w  = threadIdx.x >> 5;       // 0..15
    int y  = w & 7;                  // unit within tile
    int z  = w >> 3;                 // k-half
    int u  = u0 + y;

    const float4* Wh4 = (const float4*)(d ? Whb : Whf);
    // cooperative weight load: 4096 float4, 8 per thread; layout [y][gate][k4]
    #pragma unroll
    for (int i = threadIdx.x; i < 8 * 4 * 128; i += 512) {
        int yy = i >> 9;
        int g  = (i >> 7) & 3;
        int k4 = i & 127;
        s_w4[i] = Wh4[((size_t)(g * HH + u0 + yy)) * 128 + k4];
    }

    float c = 0.f, h = 0.f;
    float* hseqf = (float*)g_hseq;
    if (z == 0) {
        c = c0[((size_t)d * BB + b) * HH + u];
        h = h0[((size_t)d * BB + b) * HH + u];
        size_t f4 = (((size_t)d * (TT + 1) + 0) * (HH / 4) + (u >> 2)) * BB + b;
        hseqf[f4 * 4 + (u & 3)] = h;
    }
    unsigned* bar = &g_bar[d];
    grid_barrier(bar, NBLK_DIR * 1u);   // covers smem load + slot-0 publish

    const ulonglong2* swp = (const ulonglong2*)(s_w4 + (size_t)y * 4 * 128);
    const int k4base = z * 64;

    for (int s = 0; s < TT; s++) {
        int t = d ? (TT - 1 - s) : s;

        const ulonglong2* hp = (const ulonglong2*)&g_hseq[(((size_t)d * (TT + 1) + s) * (HH / 4)) * BB + b]
                               + (size_t)k4base * BB;

        unsigned long long A0 = 0ULL, A1 = 0ULL, A2 = 0ULL, A3 = 0ULL;
        #pragma unroll 8
        for (int k4 = 0; k4 < 64; k4++) {
            ulonglong2 hv = hp[k4 * BB];
            int kk = k4base + k4;
            ulonglong2 v0 = swp[0 * 128 + kk];
            ulonglong2 v1 = swp[1 * 128 + kk];
            ulonglong2 v2 = swp[2 * 128 + kk];
            ulonglong2 v3 = swp[3 * 128 + kk];
            ffma2(A0, hv.x, v0.x); ffma2(A0, hv.y, v0.y);
            ffma2(A1, hv.x, v1.x); ffma2(A1, hv.y, v1.y);
            ffma2(A2, hv.x, v2.x); ffma2(A2, hv.y, v2.y);
            ffma2(A3, hv.x, v3.x); ffma2(A3, hv.y, v3.y);
        }

        if (z == 1) {
            s_red[y * 32 + b] = make_float4(hsum2(A0), hsum2(A1), hsum2(A2), hsum2(A3));
        }
        __syncthreads();

        if (z == 0) {
            float4 xv = g_xw4[(((size_t)d * TT + t) * HH + u) * BB + b];
            float4 pr = s_red[y * 32 + b];
            float a0 = hsum2(A0) + pr.x + xv.x;
            float a1 = hsum2(A1) + pr.y + xv.y;
            float a2 = hsum2(A2) + pr.z + xv.z;
            float a3 = hsum2(A3) + pr.w + xv.w;

            float ig = sigm(a0);
            float fg = sigm(a1);
            float gg = tanhf(a2);
            float og = sigm(a3);
            c = fg * c + ig * gg;
            h = og * tanhf(c);

            size_t f4 = (((size_t)d * (TT + 1) + (s + 1)) * (HH / 4) + (u >> 2)) * BB + b;
            hseqf[f4 * 4 + (u & 3)] = h;
        }

        grid_barrier(bar, (unsigned)NBLK_DIR * (unsigned)(s + 2));
    }
}

// ---------------- 4) emission features from g_hseq ----------------
__global__ void __launch_bounds__(256) k_feats(
    const float* __restrict__ Wout, const float* __restrict__ bout)
{
    int t = blockIdx.x;
    int b = threadIdx.x & 31;
    int y = threadIdx.x >> 5;     // 0..7
    int tag0 = y * 4;

    float a0 = 0.f, a1 = 0.f, a2 = 0.f, a3 = 0.f;
    #pragma unroll
    for (int d = 0; d < 2; d++) {
        int s_idx = d ? (TT - t) : (t + 1);   // h at time t, direction d
        const float4* hb = &g_hseq[(((size_t)d * (TT + 1) + s_idx) * (HH / 4)) * BB + b];
        const float4* w0 = (const float4*)(Wout + (size_t)(tag0 + 0) * (2 * HH) + d * HH);
        const float4* w1 = (const float4*)(Wout + (size_t)(tag0 + 1) * (2 * HH) + d * HH);
        const float4* w2 = (const float4*)(Wout + (size_t)(tag0 + 2) * (2 * HH) + d * HH);
        const float4* w3 = (const float4*)(Wout + (size_t)(tag0 + 3) * (2 * HH) + d * HH);
        #pragma unroll 4
        for (int j4 = 0; j4 < HH / 4; j4++) {
            float4 hv = hb[j4 * BB];
            float4 v0 = __ldg(&w0[j4]);
            float4 v1 = __ldg(&w1[j4]);
            float4 v2 = __ldg(&w2[j4]);
            float4 v3 = __ldg(&w3[j4]);
            a0 += hv.x*v0.x + hv.y*v0.y + hv.z*v0.z + hv.w*v0.w;
            a1 += hv.x*v1.x + hv.y*v1.y + hv.z*v1.z + hv.w*v1.w;
            a2 += hv.x*v2.x + hv.y*v2.y + hv.z*v2.z + hv.w*v2.w;
            a3 += hv.x*v3.x + hv.y*v3.y + hv.z*v3.z + hv.w*v3.w;
        }
    }
    size_t ob = ((size_t)t * BB + b) * KTAG + tag0;
    g_feats[ob + 0] = a0 + bout[tag0 + 0];
    g_feats[ob + 1] = a1 + bout[tag0 + 1];
    g_feats[ob + 2] = a2 + bout[tag0 + 2];
    g_feats[ob + 3] = a3 + bout[tag0 + 3];
}

// ---------------- 5) Viterbi decode: one block per batch ----------------
__global__ void __launch_bounds__(1024) k_viterbi(
    const float* __restrict__ trans, float* __restrict__ out, int out_size)
{
    __shared__ float tr[KTAG * KTAG];
    __shared__ float v[2][KTAG];
    __shared__ unsigned char bp[TT][KTAG];

    int b   = blockIdx.x;
    int tid = threadIdx.x;
    int prev = tid & 31;      // lane
    int nxt  = tid >> 5;      // warp == next tag

    tr[tid] = trans[tid];
    if (tid < KTAG) v[0][tid] = (tid == 30) ? 0.0f : NEGV;   // START=30
    __syncthreads();

    for (int t = 0; t < TT; t++) {
        int p = t & 1;
        float sc = v[p][prev] + tr[nxt * KTAG + prev];
        int idx = prev;
        #pragma unroll
        for (int off = 16; off; off >>= 1) {
            float ov = __shfl_down_sync(0xffffffffu, sc, off);
            int   oi = __shfl_down_sync(0xffffffffu, idx, off);
            if (ov > sc || (ov == sc && oi < idx)) { sc = ov; idx = oi; }
        }
        if (prev == 0) {
            bp[t][nxt] = (unsigned char)idx;
            v[p ^ 1][nxt] = sc + g_feats[((size_t)t * BB + b) * KTAG + nxt];
        }
        __syncthreads();
    }

    // terminal = v_final + transitions[STOP=31][:]; v_final parity = 0 (TT even)
    if (tid < 32) {
        float term = v[0][tid] + tr[31 * KTAG + tid];
        int idx = tid;
        #pragma unroll
        for (int off = 16; off; off >>= 1) {
            float ov = __shfl_down_sync(0xffffffffu, term, off);
            int   oi = __shfl_down_sync(0xffffffffu, idx, off);
            if (ov > term || (ov == term && oi < idx)) { term = ov; idx = oi; }
        }
        if (tid == 0) {
            bool both = (out_size >= BB * (TT + 1));
            if (both || out_size == BB) out[b] = term;   // path_score
            if (both) {
                int base = BB + b * TT;
                int tag = idx;
                for (int t = TT - 1; t >= 0; t--) {
                    out[base + t] = (float)tag;
                    tag = bp[t][tag];
                }
            } else if (out_size == BB * TT) {
                int tag = idx;
                for (int t = TT - 1; t >= 0; t--) {
                    out[b * TT + t] = (float)tag;
                    tag = bp[t][tag];
                }
            }
        }
    }
}

// ---------------- launch ----------------
extern "C" void kernel_launch(void* const* d_in, const int* in_sizes, int n_in,
                              void* d_out, int out_size) {
    const int*   sent = (const int*)  d_in[0];
    const float* emb  = (const float*)d_in[1];
    const float* Wif  = (const float*)d_in[2];
    const float* Whf  = (const float*)d_in[3];
    const float* bf   = (const float*)d_in[4];
    const float* Wib  = (const float*)d_in[5];
    const float* Whb  = (const float*)d_in[6];
    const float* bb   = (const float*)d_in[7];
    const float* Wout = (const float*)d_in[8];
    const float* bout = (const float*)d_in[9];
    const float* trans= (const float*)d_in[10];
    const float* h0   = (const float*)d_in[11];
    const float* c0   = (const float*)d_in[12];
    (void)in_sizes; (void)n_in;

    const int LSTM_SMEM = (8 * 4 * 128 + 256) * 16;   // 64 KB weights + 4 KB reduce
    cudaFuncSetAttribute(k_lstm, cudaFuncAttributeMaxDynamicSharedMemorySize, LSTM_SMEM);

    k_reset  <<<1, 1>>>();
    k_embed  <<<TT, 256>>>(sent, emb);
    k_xw     <<<2 * 64 * 64, 256>>>(Wif, bf, Wib, bb);
    k_lstm   <<<2 * NBLK_DIR, 512, LSTM_SMEM>>>(Whf, Whb, h0, c0);
    k_feats  <<<TT, 256>>>(Wout, bout);
    k_viterbi<<<BB, 1024>>>(trans, (float*)d_out, out_size);
}

// round 17
// speedup vs baseline: 4.6798x; 1.1065x over previous
#include <cuda_runtime.h>
#include <cuda_bf16.h>
#include <math.h>

// Problem constants
#define TT   256       // sequence length
#define BB   32        // batch
#define EE   256       // embedding dim
#define HH   512       // hidden dim
#define KTAG 32        // number of tags
#define NEGV (-10000.0f)
#define NBLK_DIR 64    // persistent blocks per direction (128 total, co-resident)

// ---------------- device scratch (static, no allocations) ----------------
__device__ float4  g_x4[TT * (EE / 4) * BB];              // embedded input  [t][e4][b]
__device__ float4  g_xw4[(size_t)2 * TT * HH * BB];       // xW_ih^T + b     [d][t][u][b] = (i,f,g,o)
__device__ float4  g_hseq[2 * (TT + 1) * (HH / 4) * BB];  // h per step      [d][s][k4][b] (write-once)
__device__ float   g_feats[TT * BB * KTAG];               // emission feats  [t][b][tag]
__device__ unsigned g_bar[2];                             // one barrier counter per direction

__device__ __forceinline__ float sigm(float x) { return 1.0f / (1.0f + expf(-x)); }

// packed fp32x2 FMA (sm_103a): a = x*y + a elementwise on two packed floats
__device__ __forceinline__ void ffma2(unsigned long long& a, unsigned long long x, unsigned long long y) {
    asm("fma.rn.f32x2 %0, %1, %2, %0;" : "+l"(a) : "l"(x), "l"(y));
}
__device__ __forceinline__ float hsum2(unsigned long long a) {
    float lo, hi;
    asm("mov.b64 {%0,%1}, %2;" : "=f"(lo), "=f"(hi) : "l"(a));
    return lo + hi;
}

// Cumulative-counter barrier over the NBLK_DIR blocks of one direction.
__device__ __forceinline__ void grid_barrier(unsigned* bar, unsigned target) {
    __syncthreads();
    if (threadIdx.x == 0) {
        __threadfence();                 // release all prior global writes
        atomicAdd(bar, 1u);
        unsigned v;
        do {
            asm volatile("ld.acquire.gpu.u32 %0, [%1];" : "=r"(v) : "l"(bar) : "memory");
        } while (v < target);
    }
    __syncthreads();
}

__global__ void k_reset() { g_bar[0] = 0u; g_bar[1] = 0u; }

// ---------------- 1) embedding gather ----------------
__global__ void k_embed(const int* __restrict__ sent, const float* __restrict__ emb) {
    int t = blockIdx.x;
    int b = threadIdx.x & 31;
    int w = threadIdx.x >> 5;                  // 0..7
    int tok = sent[b * TT + t];
    const float4* src = (const float4*)(emb + (size_t)tok * EE);
    #pragma unroll
    for (int e4 = w; e4 < EE / 4; e4 += 8) {
        g_x4[(t * (EE / 4) + e4) * BB + b] = src[e4];
    }
}

// ---------------- 2) input GEMM: 4 timesteps/thread, f32x2 FMA, float4 (i,f,g,o) output ----------------
// grid = 2 dirs * 64 t-tiles(4 each) * 64 u-tiles(8 units) = 8192 blocks
__global__ void __launch_bounds__(256) k_xw(
    const float* __restrict__ Wf, const float* __restrict__ bf,
    const float* __restrict__ Wb, const float* __restrict__ bbias)
{
    int bi  = blockIdx.x;
    int d   = bi >> 12;
    int rem = bi & 4095;
    int t0  = (rem >> 6) * 4;
    int u0  = (rem & 63) * 8;
    int b   = threadIdx.x & 31;
    int y   = threadIdx.x >> 5;
    int u   = u0 + y;

    const float* W    = d ? Wb : Wf;
    const float* bias = d ? bbias : bf;
    const ulonglong2* w0 = (const ulonglong2*)(W + (size_t)(0 * HH + u) * EE);
    const ulonglong2* w1 = (const ulonglong2*)(W + (size_t)(1 * HH + u) * EE);
    const ulonglong2* w2 = (const ulonglong2*)(W + (size_t)(2 * HH + u) * EE);
    const ulonglong2* w3 = (const ulonglong2*)(W + (size_t)(3 * HH + u) * EE);
    const ulonglong2* xp0 = (const ulonglong2*)&g_x4[(t0 + 0) * (EE / 4) * BB + b];
    const ulonglong2* xp1 = (const ulonglong2*)&g_x4[(t0 + 1) * (EE / 4) * BB + b];
    const ulonglong2* xp2 = (const ulonglong2*)&g_x4[(t0 + 2) * (EE / 4) * BB + b];
    const ulonglong2* xp3 = (const ulonglong2*)&g_x4[(t0 + 3) * (EE / 4) * BB + b];

    unsigned long long A[4][4];   // [t][gate] packed f32x2 accumulators
    #pragma unroll
    for (int i = 0; i < 4; i++)
        #pragma unroll
        for (int j = 0; j < 4; j++) A[i][j] = 0ULL;

    #pragma unroll 4
    for (int k4 = 0; k4 < EE / 4; k4++) {
        ulonglong2 v0 = __ldg(&w0[k4]);
        ulonglong2 v1 = __ldg(&w1[k4]);
        ulonglong2 v2 = __ldg(&w2[k4]);
        ulonglong2 v3 = __ldg(&w3[k4]);
        ulonglong2 xv;
        xv = xp0[k4 * BB];
        ffma2(A[0][0], xv.x, v0.x); ffma2(A[0][0], xv.y, v0.y);
        ffma2(A[0][1], xv.x, v1.x); ffma2(A[0][1], xv.y, v1.y);
        ffma2(A[0][2], xv.x, v2.x); ffma2(A[0][2], xv.y, v2.y);
        ffma2(A[0][3], xv.x, v3.x); ffma2(A[0][3], xv.y, v3.y);
        xv = xp1[k4 * BB];
        ffma2(A[1][0], xv.x, v0.x); ffma2(A[1][0], xv.y, v0.y);
        ffma2(A[1][1], xv.x, v1.x); ffma2(A[1][1], xv.y, v1.y);
        ffma2(A[1][2], xv.x, v2.x); ffma2(A[1][2], xv.y, v2.y);
        ffma2(A[1][3], xv.x, v3.x); ffma2(A[1][3], xv.y, v3.y);
        xv = xp2[k4 * BB];
        ffma2(A[2][0], xv.x, v0.x); ffma2(A[2][0], xv.y, v0.y);
        ffma2(A[2][1], xv.x, v1.x); ffma2(A[2][1], xv.y, v1.y);
        ffma2(A[2][2], xv.x, v2.x); ffma2(A[2][2], xv.y, v2.y);
        ffma2(A[2][3], xv.x, v3.x); ffma2(A[2][3], xv.y, v3.y);
        xv = xp3[k4 * BB];
        ffma2(A[3][0], xv.x, v0.x); ffma2(A[3][0], xv.y, v0.y);
        ffma2(A[3][1], xv.x, v1.x); ffma2(A[3][1], xv.y, v1.y);
        ffma2(A[3][2], xv.x, v2.x); ffma2(A[3][2], xv.y, v2.y);
        ffma2(A[3][3], xv.x, v3.x); ffma2(A[3][3], xv.y, v3.y);
    }

    float bi0 = bias[0 * HH + u];
    float bi1 = bias[1 * HH + u];
    float bi2 = bias[2 * HH + u];
    float bi3 = bias[3 * HH + u];
    #pragma unroll
    for (int tt = 0; tt < 4; tt++) {
        size_t o = (((size_t)d * TT + (t0 + tt)) * HH + u) * BB + b;
        g_xw4[o] = make_float4(hsum2(A[tt][0]) + bi0, hsum2(A[tt][1]) + bi1,
                               hsum2(A[tt][2]) + bi2, hsum2(A[tt][3]) + bi3);
    }
}

// ---------------- 3) persistent bidirectional LSTM (h staged via smem) ----------------
// 128 blocks x 512 threads: (dir, 8-unit tile).
// Warp = (y2 in 0..3 -> unit pair {2y2, 2y2+1}, z in 0..3 -> k-quarter).
// Per step: cooperatively stage h_s (64 KB) gmem->smem once, then all warps
// compute from smem. Partials from z=1..3 combined in smem by z=0.
__global__ void __launch_bounds__(512, 1) k_lstm(
    const float* __restrict__ Whf, const float* __restrict__ Whb,
    const float* __restrict__ h0, const float* __restrict__ c0)
{
    extern __shared__ float4 s_mem[];
    float4* s_w4  = s_mem;                      // [u(8)][gate(4)][k4(128)]   4096 f4 = 64 KB
    float4* s_h   = s_mem + 4096;               // [k4(128)][b(32)]           4096 f4 = 64 KB
    float4* s_red = s_mem + 8192;               // [zz(3)][y2(4)][ui(2)][b]    768 f4 = 12 KB

    int bi = blockIdx.x;
    int d  = bi >> 6;
    int u0 = (bi & 63) * 8;
    int b  = threadIdx.x & 31;
    int w  = threadIdx.x >> 5;       // 0..15
    int y2 = w >> 2;                 // 0..3 unit pair
    int z  = w & 3;                  // 0..3 k-quarter
    int ua = u0 + 2 * y2;
    int ub = ua + 1;

    const float4* Wh4 = (const float4*)(d ? Whb : Whf);
    // cooperative weight load: 4096 float4; layout [u][gate][k4]
    #pragma unroll
    for (int i = threadIdx.x; i < 8 * 4 * 128; i += 512) {
        int uu = i >> 9;
        int g  = (i >> 7) & 3;
        int k4 = i & 127;
        s_w4[i] = Wh4[((size_t)(g * HH + u0 + uu)) * 128 + k4];
    }

    float ca = 0.f, ha = 0.f, cb = 0.f, hb = 0.f;
    float* hseqf = (float*)g_hseq;
    if (z == 0) {
        ca = c0[((size_t)d * BB + b) * HH + ua];
        ha = h0[((size_t)d * BB + b) * HH + ua];
        cb = c0[((size_t)d * BB + b) * HH + ub];
        hb = h0[((size_t)d * BB + b) * HH + ub];
        size_t fa = (((size_t)d * (TT + 1) + 0) * (HH / 4) + (ua >> 2)) * BB + b;
        hseqf[fa * 4 + (ua & 3)] = ha;
        size_t fb = (((size_t)d * (TT + 1) + 0) * (HH / 4) + (ub >> 2)) * BB + b;
        hseqf[fb * 4 + (ub & 3)] = hb;
    }
    unsigned* bar = &g_bar[d];
    grid_barrier(bar, NBLK_DIR * 1u);   // covers smem weight load + slot-0 publish

    const float4* swa = s_w4 + (size_t)(2 * y2)     * 512;
    const float4* swb = s_w4 + (size_t)(2 * y2 + 1) * 512;
    const int kbase = z * 32;

    for (int s = 0; s < TT; s++) {
        int t = d ? (TT - 1 - s) : s;

        // stage h_s: 4096 float4, 8 per thread
        {
            const float4* src = &g_hseq[(((size_t)d * (TT + 1) + s) * (HH / 4)) * BB];
            #pragma unroll
            for (int i = 0; i < 8; i++) {
                int idx = threadIdx.x + i * 512;
                s_h[idx] = src[idx];
            }
        }
        // prefetch xw for this step (z==0 consumes it after the reduce)
        float4 xva, xvb;
        if (z == 0) {
            xva = g_xw4[(((size_t)d * TT + t) * HH + ua) * BB + b];
            xvb = g_xw4[(((size_t)d * TT + t) * HH + ub) * BB + b];
        }
        __syncthreads();

        unsigned long long Aa0 = 0ULL, Aa1 = 0ULL, Aa2 = 0ULL, Aa3 = 0ULL;
        unsigned long long Ab0 = 0ULL, Ab1 = 0ULL, Ab2 = 0ULL, Ab3 = 0ULL;
        #pragma unroll 8
        for (int k4 = 0; k4 < 32; k4++) {
            int kk = kbase + k4;
            ulonglong2 hv = *(const ulonglong2*)&s_h[kk * BB + b];
            ulonglong2 va, vb;
            va = *(const ulonglong2*)&swa[0 * 128 + kk];
            vb = *(const ulonglong2*)&swb[0 * 128 + kk];
            ffma2(Aa0, hv.x, va.x); ffma2(Aa0, hv.y, va.y);
            ffma2(Ab0, hv.x, vb.x); ffma2(Ab0, hv.y, vb.y);
            va = *(const ulonglong2*)&swa[1 * 128 + kk];
            vb = *(const ulonglong2*)&swb[1 * 128 + kk];
            ffma2(Aa1, hv.x, va.x); ffma2(Aa1, hv.y, va.y);
            ffma2(Ab1, hv.x, vb.x); ffma2(Ab1, hv.y, vb.y);
            va = *(const ulonglong2*)&swa[2 * 128 + kk];
            vb = *(const ulonglong2*)&swb[2 * 128 + kk];
            ffma2(Aa2, hv.x, va.x); ffma2(Aa2, hv.y, va.y);
            ffma2(Ab2, hv.x, vb.x); ffma2(Ab2, hv.y, vb.y);
            va = *(const ulonglong2*)&swa[3 * 128 + kk];
            vb = *(const ulonglong2*)&swb[3 * 128 + kk];
            ffma2(Aa3, hv.x, va.x); ffma2(Aa3, hv.y, va.y);
            ffma2(Ab3, hv.x, vb.x); ffma2(Ab3, hv.y, vb.y);
        }

        if (z != 0) {
            float4* r = &s_red[(((z - 1) * 4 + y2) * 2 + 0) * 32 + b];
            r[0]  = make_float4(hsum2(Aa0), hsum2(Aa1), hsum2(Aa2), hsum2(Aa3));
            r[32] = make_float4(hsum2(Ab0), hsum2(Ab1), hsum2(Ab2), hsum2(Ab3));
        }
        __syncthreads();

        if (z == 0) {
            float a0 = hsum2(Aa0) + xva.x;
            float a1 = hsum2(Aa1) + xva.y;
            float a2 = hsum2(Aa2) + xva.z;
            float a3 = hsum2(Aa3) + xva.w;
            float b0 = hsum2(Ab0) + xvb.x;
            float b1 = hsum2(Ab1) + xvb.y;
            float b2 = hsum2(Ab2) + xvb.z;
            float b3 = hsum2(Ab3) + xvb.w;
            #pragma unroll
            for (int zz = 0; zz < 3; zz++) {
                float4 pa = s_red[((zz * 4 + y2) * 2 + 0) * 32 + b];
                float4 pb = s_red[((zz * 4 + y2) * 2 + 1) * 32 + b];
                a0 += pa.x; a1 += pa.y; a2 += pa.z; a3 += pa.w;
                b0 += pb.x; b1 += pb.y; b2 += pb.z; b3 += pb.w;
            }

            float iga = sigm(a0), fga = sigm(a1), gga = tanhf(a2), oga = sigm(a3);
            ca = fga * ca + iga * gga;
            ha = oga * tanhf(ca);
            float igb = sigm(b0), fgb = sigm(b1), ggb = tanhf(b2), ogb = sigm(b3);
            cb = fgb * cb + igb * ggb;
            hb = ogb * tanhf(cb);

            size_t fa = (((size_t)d * (TT + 1) + (s + 1)) * (HH / 4) + (ua >> 2)) * BB + b;
            hseqf[fa * 4 + (ua & 3)] = ha;
            size_t fb = (((size_t)d * (TT + 1) + (s + 1)) * (HH / 4) + (ub >> 2)) * BB + b;
            hseqf[fb * 4 + (ub & 3)] = hb;
        }

        grid_barrier(bar, (unsigned)NBLK_DIR * (unsigned)(s + 2));
    }
}

// ---------------- 4) emission features from g_hseq ----------------
__global__ void __launch_bounds__(256) k_feats(
    const float* __restrict__ Wout, const float* __restrict__ bout)
{
    int t = blockIdx.x;
    int b = threadIdx.x & 31;
    int y = threadIdx.x >> 5;     // 0..7
    int tag0 = y * 4;

    float a0 = 0.f, a1 = 0.f, a2 = 0.f, a3 = 0.f;
    #pragma unroll
    for (int d = 0; d < 2; d++) {
        int s_idx = d ? (TT - t) : (t + 1);   // h at time t, direction d
        const float4* hbp = &g_hseq[(((size_t)d * (TT + 1) + s_idx) * (HH / 4)) * BB + b];
        const float4* w0 = (const float4*)(Wout + (size_t)(tag0 + 0) * (2 * HH) + d * HH);
        const float4* w1 = (const float4*)(Wout + (size_t)(tag0 + 1) * (2 * HH) + d * HH);
        const float4* w2 = (const float4*)(Wout + (size_t)(tag0 + 2) * (2 * HH) + d * HH);
        const float4* w3 = (const float4*)(Wout + (size_t)(tag0 + 3) * (2 * HH) + d * HH);
        #pragma unroll 4
        for (int j4 = 0; j4 < HH / 4; j4++) {
            float4 hv = hbp[j4 * BB];
            float4 v0 = __ldg(&w0[j4]);
            float4 v1 = __ldg(&w1[j4]);
            float4 v2 = __ldg(&w2[j4]);
            float4 v3 = __ldg(&w3[j4]);
            a0 += hv.x*v0.x + hv.y*v0.y + hv.z*v0.z + hv.w*v0.w;
            a1 += hv.x*v1.x + hv.y*v1.y + hv.z*v1.z + hv.w*v1.w;
            a2 += hv.x*v2.x + hv.y*v2.y + hv.z*v2.z + hv.w*v2.w;
            a3 += hv.x*v3.x + hv.y*v3.y + hv.z*v3.z + hv.w*v3.w;
        }
    }
    size_t ob = ((size_t)t * BB + b) * KTAG + tag0;
    g_feats[ob + 0] = a0 + bout[tag0 + 0];
    g_feats[ob + 1] = a1 + bout[tag0 + 1];
    g_feats[ob + 2] = a2 + bout[tag0 + 2];
    g_feats[ob + 3] = a3 + bout[tag0 + 3];
}

// ---------------- 5) Viterbi decode: one block per batch ----------------
__global__ void __launch_bounds__(1024) k_viterbi(
    const float* __restrict__ trans, float* __restrict__ out, int out_size)
{
    __shared__ float tr[KTAG * KTAG];
    __shared__ float v[2][KTAG];
    __shared__ unsigned char bp[TT][KTAG];

    int b   = blockIdx.x;
    int tid = threadIdx.x;
    int prev = tid & 31;      // lane
    int nxt  = tid >> 5;      // warp == next tag

    tr[tid] = trans[tid];
    if (tid < KTAG) v[0][tid] = (tid == 30) ? 0.0f : NEGV;   // START=30
    __syncthreads();

    for (int t = 0; t < TT; t++) {
        int p = t & 1;
        float sc = v[p][prev] + tr[nxt * KTAG + prev];
        int idx = prev;
        #pragma unroll
        for (int off = 16; off; off >>= 1) {
            float ov = __shfl_down_sync(0xffffffffu, sc, off);
            int   oi = __shfl_down_sync(0xffffffffu, idx, off);
            if (ov > sc || (ov == sc && oi < idx)) { sc = ov; idx = oi; }
        }
        if (prev == 0) {
            bp[t][nxt] = (unsigned char)idx;
            v[p ^ 1][nxt] = sc + g_feats[((size_t)t * BB + b) * KTAG + nxt];
        }
        __syncthreads();
    }

    // terminal = v_final + transitions[STOP=31][:]; v_final parity = 0 (TT even)
    if (tid < 32) {
        float term = v[0][tid] + tr[31 * KTAG + tid];
        int idx = tid;
        #pragma unroll
        for (int off = 16; off; off >>= 1) {
            float ov = __shfl_down_sync(0xffffffffu, term, off);
            int   oi = __shfl_down_sync(0xffffffffu, idx, off);
            if (ov > term || (ov == term && oi < idx)) { term = ov; idx = oi; }
        }
        if (tid == 0) {
            bool both = (out_size >= BB * (TT + 1));
            if (both || out_size == BB) out[b] = term;   // path_score
            if (both) {
                int base = BB + b * TT;
                int tag = idx;
                for (int t = TT - 1; t >= 0; t--) {
                    out[base + t] = (float)tag;
                    tag = bp[t][tag];
                }
            } else if (out_size == BB * TT) {
                int tag = idx;
                for (int t = TT - 1; t >= 0; t--) {
                    out[b * TT + t] = (float)tag;
                    tag = bp[t][tag];
                }
            }
        }
    }
}

// ---------------- launch ----------------
extern "C" void kernel_launch(void* const* d_in, const int* in_sizes, int n_in,
                              void* d_out, int out_size) {
    const int*   sent = (const int*)  d_in[0];
    const float* emb  = (const float*)d_in[1];
    const float* Wif  = (const float*)d_in[2];
    const float* Whf  = (const float*)d_in[3];
    const float* bf   = (const float*)d_in[4];
    const float* Wib  = (const float*)d_in[5];
    const float* Whb  = (const float*)d_in[6];
    const float* bb   = (const float*)d_in[7];
    const float* Wout = (const float*)d_in[8];
    const float* bout = (const float*)d_in[9];
    const float* trans= (const float*)d_in[10];
    const float* h0   = (const float*)d_in[11];
    const float* c0   = (const float*)d_in[12];
    (void)in_sizes; (void)n_in;

    const int LSTM_SMEM = (4096 + 4096 + 768) * 16;   // weights 64K + h stage 64K + reduce 12K
    cudaFuncSetAttribute(k_lstm, cudaFuncAttributeMaxDynamicSharedMemorySize, LSTM_SMEM);

    k_reset  <<<1, 1>>>();
    k_embed  <<<TT, 256>>>(sent, emb);
    k_xw     <<<2 * 64 * 64, 256>>>(Wif, bf, Wib, bb);
    k_lstm   <<<2 * NBLK_DIR, 512, LSTM_SMEM>>>(Whf, Whb, h0, c0);
    k_feats  <<<TT, 256>>>(Wout, bout);
    k_viterbi<<<BB, 1024>>>(trans, (float*)d_out, out_size);
}